// round 4
// baseline (speedup 1.0000x reference)
#include <cuda_runtime.h>
#include <cuda_bf16.h>
#include <float.h>

// Problem constants (structural, from reference)
#define HD    128     // hidden H
#define NECKD 512
#define FIN   59
#define NMAX  8192
#define KNB   32      // neighbors per node

// ---------------- scratch (device globals; no allocation allowed) ----------------
__device__ float g_v   [NMAX * HD];
__device__ float g_asrc[NMAX * HD];
__device__ float g_adst[NMAX * HD];
__device__ float g_hout[NMAX * HD];
__device__ float g_hneck[NMAX * NECKD];
__device__ float g_gfeat[NMAX * NECKD];
__device__ int   g_pb[NMAX];
__device__ int   g_seg_start[NMAX];
__device__ int   g_seg_end[NMAX];
__device__ float g_mask_g[NMAX];

// ---------------- K0a: relabel pool_batch -> pb via prefix scan of change flags ----
__global__ void scan_pb_kernel(const int* __restrict__ pool_batch, int n) {
    // one block of 1024 threads, each handles 8 contiguous elements
    __shared__ int sums[1024];
    int t = threadIdx.x;
    int base = t * 8;
    int loc[8];
    int run = 0;
#pragma unroll
    for (int j = 0; j < 8; ++j) {
        int i = base + j;
        int chg = 0;
        if (i < n && i > 0) chg = (pool_batch[i] != pool_batch[i - 1]) ? 1 : 0;
        run += chg;
        loc[j] = run;
    }
    sums[t] = run;
    __syncthreads();
    // Hillis-Steele inclusive scan over 1024 partials
    for (int off = 1; off < 1024; off <<= 1) {
        int v = (t >= off) ? sums[t - off] : 0;
        __syncthreads();
        sums[t] += v;
        __syncthreads();
    }
    int offset = (t > 0) ? sums[t - 1] : 0;
#pragma unroll
    for (int j = 0; j < 8; ++j) {
        int i = base + j;
        if (i < n) g_pb[i] = offset + loc[j];
    }
}

// ---------------- K0b: segment boundaries from pb (non-decreasing) -----------------
__global__ void seg_bounds_kernel(int n) {
    int i = blockIdx.x * blockDim.x + threadIdx.x;
    if (i >= n) return;
    int g = g_pb[i];
    if (i == 0 || g_pb[i - 1] != g) g_seg_start[g] = i;
    if (i == n - 1 || g_pb[i + 1] != g) g_seg_end[g] = i + 1;
}

// ---------------- K1: node GEMMs  v = x@lin_w+b ; asrc = x@src_w ; adst = x@dst_w --
__global__ void __launch_bounds__(128, 2)
node_gemm_kernel(const float* __restrict__ x,
                 const float* __restrict__ lin_w, const float* __restrict__ lin_b,
                 const float* __restrict__ src_w, const float* __restrict__ dst_w,
                 int n) {
    int which = blockIdx.y;
    const float* W = (which == 0) ? lin_w : (which == 1) ? src_w : dst_w;
    float* out = (which == 0) ? g_v : (which == 1) ? g_asrc : g_adst;
    int h = threadIdx.x;

    float Wc[FIN];
#pragma unroll
    for (int c = 0; c < FIN; ++c) Wc[c] = W[c * HD + h];
    float bias = (which == 0) ? lin_b[h] : 0.0f;

    int r0 = blockIdx.x * 32;
    __shared__ float xs[32][FIN + 1];
    for (int idx = h; idx < 32 * FIN; idx += 128) {
        int r = idx / FIN, c = idx % FIN;
        xs[r][c] = x[(r0 + r) * FIN + c];
    }
    __syncthreads();
    for (int r = 0; r < 32; ++r) {
        float a = bias;
#pragma unroll
        for (int c = 0; c < FIN; ++c) a = fmaf(xs[r][c], Wc[c], a);
        out[(r0 + r) * HD + h] = a;
    }
}

// ---------------- K2: fused edge attention (the hot kernel) ------------------------
// One thread = one output channel h. Persistent blocks; attnn_w column in registers.
// Per dst node: loop its 32 contiguous edges, build t = a_dst - a_src + delta in smem,
// alpha_h = bn_relu(t . Wcol), online softmax per channel, accumulate attn*(v+delta).
__global__ void __launch_bounds__(128, 2)
attn_kernel(const float* __restrict__ pos, const float* __restrict__ normal,
            const int* __restrict__ src,
            const float* __restrict__ posnn_w, const float* __restrict__ posnn_b,
            const float* __restrict__ posnn_g, const float* __restrict__ posnn_bb,
            const float* __restrict__ attnn_w, const float* __restrict__ attnn_b,
            const float* __restrict__ attnn_g, const float* __restrict__ attnn_bb,
            int n, int k) {
    const int h = threadIdx.x;
    __shared__ float4 tsb[2][HD / 4];

    // per-thread constants
    float Wc[HD];
#pragma unroll
    for (int c = 0; c < HD; ++c) Wc[c] = attnn_w[c * HD + h];
    float Wp[6];
#pragma unroll
    for (int j = 0; j < 6; ++j) Wp[j] = posnn_w[j * HD + h];
    const float inv = rsqrtf(1.0f + 1e-5f);
    const float pb_  = posnn_b[h];
    const float pg   = posnn_g[h] * inv;
    const float pbb  = posnn_bb[h];
    const float ab_  = attnn_b[h];
    const float ag   = attnn_g[h] * inv;
    const float abb  = attnn_bb[h];

    for (int i = blockIdx.x; i < n; i += gridDim.x) {
        float ad = g_adst[i * HD + h];
        float px = pos[3 * i], py = pos[3 * i + 1], pz = pos[3 * i + 2];
        float nx = normal[3 * i], ny = normal[3 * i + 1], nz = normal[3 * i + 2];

        float m = -FLT_MAX, ssum = 0.0f, acc = 0.0f;

        for (int e = 0; e < k; ++e) {
            int s = src[i * KNB + e];
            // rel = [pos_i - pos_s, nrm_i - nrm_s]  (uniform loads, L1-broadcast)
            float r0 = px - pos[3 * s],     r1 = py - pos[3 * s + 1], r2 = pz - pos[3 * s + 2];
            float r3 = nx - normal[3 * s],  r4 = ny - normal[3 * s + 1], r5 = nz - normal[3 * s + 2];
            // delta_h = bn_relu(rel @ posnn_w + b)
            float d = pb_;
            d = fmaf(r0, Wp[0], d); d = fmaf(r1, Wp[1], d); d = fmaf(r2, Wp[2], d);
            d = fmaf(r3, Wp[3], d); d = fmaf(r4, Wp[4], d); d = fmaf(r5, Wp[5], d);
            d = fmaxf(fmaf(d, pg, pbb), 0.0f);

            float t = ad - g_asrc[s * HD + h] + d;
            int buf = e & 1;
            ((float*)(tsb[buf]))[h] = t;
            __syncthreads();   // double-buffered: one barrier per edge is sufficient

            // alpha_h = bn_relu(t . Wcol + b)
            const float4* t4 = (const float4*)(tsb[buf]);
            float a0 = 0.f, a1 = 0.f, a2 = 0.f, a3 = 0.f;
#pragma unroll
            for (int c4 = 0; c4 < HD / 4; ++c4) {
                float4 tv = t4[c4];   // broadcast LDS.128
                a0 = fmaf(tv.x, Wc[4 * c4 + 0], a0);
                a1 = fmaf(tv.y, Wc[4 * c4 + 1], a1);
                a2 = fmaf(tv.z, Wc[4 * c4 + 2], a2);
                a3 = fmaf(tv.w, Wc[4 * c4 + 3], a3);
            }
            float alpha = (a0 + a1) + (a2 + a3) + ab_;
            alpha = fmaxf(fmaf(alpha, ag, abb), 0.0f);

            // online softmax + weighted accumulation of (v[src] + delta)
            float w = g_v[s * HD + h] + d;
            float nm = fmaxf(m, alpha);
            float c1 = __expf(m - nm);       // 0 on first edge (m = -FLT_MAX)
            float c2 = __expf(alpha - nm);
            ssum = ssum * c1 + c2;
            acc  = acc  * c1 + c2 * w;
            m = nm;
        }
        g_hout[i * HD + h] = acc / (ssum + 1e-16f);
    }
}

// ---------------- K3: neck GEMM + bn_relu :  hneck = bn_relu(hout @ neck_w + b) ----
__global__ void __launch_bounds__(128, 2)
neck_kernel(const float* __restrict__ W, const float* __restrict__ b,
            const float* __restrict__ g, const float* __restrict__ bb, int n) {
    int col = blockIdx.y * 128 + threadIdx.x;   // 0..511
    float Wc[HD];
#pragma unroll
    for (int c = 0; c < HD; ++c) Wc[c] = W[c * NECKD + col];
    const float inv = rsqrtf(1.0f + 1e-5f);
    float bias = b[col], gg = g[col] * inv, sh = bb[col];

    int r0 = blockIdx.x * 16;
    __shared__ __align__(16) float hs[16][HD];
    for (int idx = threadIdx.x; idx < 16 * HD; idx += 128)
        ((float*)hs)[idx] = g_hout[r0 * HD + idx];
    __syncthreads();

    for (int r = 0; r < 16; ++r) {
        const float4* h4 = (const float4*)(hs[r]);
        float a0 = 0.f, a1 = 0.f, a2 = 0.f, a3 = 0.f;
#pragma unroll
        for (int c4 = 0; c4 < HD / 4; ++c4) {
            float4 tv = h4[c4];
            a0 = fmaf(tv.x, Wc[4 * c4 + 0], a0);
            a1 = fmaf(tv.y, Wc[4 * c4 + 1], a1);
            a2 = fmaf(tv.z, Wc[4 * c4 + 2], a2);
            a3 = fmaf(tv.w, Wc[4 * c4 + 3], a3);
        }
        float a = (a0 + a1) + (a2 + a3) + bias;
        g_hneck[(r0 + r) * NECKD + col] = fmaxf(fmaf(a, gg, sh), 0.0f);
    }
}

// ---------------- K-segmax: per-residue max pool over consecutive segments ---------
__global__ void segmax_kernel(const float* __restrict__ mask_t, int G) {
    int gidx = blockIdx.x;
    if (gidx >= G) return;
    int c = blockIdx.y * 128 + threadIdx.x;
    int s0 = g_seg_start[gidx], s1 = g_seg_end[gidx];
    float mx = -FLT_MAX;
    for (int i = s0; i < s1; ++i) mx = fmaxf(mx, g_hneck[i * NECKD + c]);
    g_gfeat[gidx * NECKD + c] = mx;
    if (blockIdx.y == 0 && threadIdx.x == 0) {
        float mm = -FLT_MAX;
        for (int i = s0; i < s1; ++i) mm = fmaxf(mm, mask_t[i]);
        g_mask_g[gidx] = mm;
    }
}

// ---------------- K4: mlp1 (bn_relu) + mlp2 + mask -------------------------------
__global__ void __launch_bounds__(256)
head_kernel(const float* __restrict__ W1, const float* __restrict__ b1,
            const float* __restrict__ g1, const float* __restrict__ bb1,
            const float* __restrict__ W2, const float* __restrict__ b2,
            float* __restrict__ out, int G) {
    int t = threadIdx.x;                 // 0..255  (mlp1 output channel)
    int g0 = blockIdx.x * 8;
    __shared__ float gs[8][NECKD];
    for (int idx = t; idx < 8 * NECKD; idx += 256) {
        int gi = idx >> 9, c = idx & (NECKD - 1);
        gs[gi][c] = (g0 + gi < G) ? g_gfeat[(g0 + gi) * NECKD + c] : 0.0f;
    }
    __syncthreads();

    float acc[8] = {0, 0, 0, 0, 0, 0, 0, 0};
    for (int c = 0; c < NECKD; ++c) {
        float w = W1[c * 256 + t];       // loaded once, reused for 8 groups
#pragma unroll
        for (int gi = 0; gi < 8; ++gi) acc[gi] = fmaf(gs[gi][c], w, acc[gi]);
    }

    const float inv = rsqrtf(1.0f + 1e-5f);
    float bias = b1[t], gg = g1[t] * inv, sh = bb1[t], w2 = W2[t];

    __shared__ float red[256];
    for (int gi = 0; gi < 8; ++gi) {
        float m1 = fmaxf(fmaf(acc[gi] + bias, gg, sh), 0.0f);
        red[t] = m1 * w2;
        __syncthreads();
        for (int off = 128; off > 0; off >>= 1) {
            if (t < off) red[t] += red[t + off];
            __syncthreads();
        }
        if (t == 0) {
            int g = g0 + gi;
            if (g < G) out[g] = (g_mask_g[g] == 1.0f) ? (red[0] + b2[0]) : 0.0f;
        }
        __syncthreads();
    }
}

// ---------------- launch --------------------------------------------------------
extern "C" void kernel_launch(void* const* d_in, const int* in_sizes, int n_in,
                              void* d_out, int out_size) {
    const float* x        = (const float*)d_in[0];
    const float* pos      = (const float*)d_in[1];
    const float* normal   = (const float*)d_in[2];
    const float* mask_t   = (const float*)d_in[3];
    const int*   pool_b   = (const int*)  d_in[4];
    const int*   src      = (const int*)  d_in[5];
    // d_in[6] = dst (unused: edges are grouped per dst by construction)
    const float* lin_w    = (const float*)d_in[7];
    const float* lin_b    = (const float*)d_in[8];
    const float* src_w    = (const float*)d_in[9];
    const float* dst_w    = (const float*)d_in[10];
    const float* posnn_w  = (const float*)d_in[11];
    const float* posnn_b  = (const float*)d_in[12];
    const float* posnn_g  = (const float*)d_in[13];
    const float* posnn_bb = (const float*)d_in[14];
    const float* attnn_w  = (const float*)d_in[15];
    const float* attnn_b  = (const float*)d_in[16];
    const float* attnn_g  = (const float*)d_in[17];
    const float* attnn_bb = (const float*)d_in[18];
    const float* neck_w   = (const float*)d_in[19];
    const float* neck_b   = (const float*)d_in[20];
    const float* neck_g   = (const float*)d_in[21];
    const float* neck_bb  = (const float*)d_in[22];
    const float* mlp1_w   = (const float*)d_in[23];
    const float* mlp1_b   = (const float*)d_in[24];
    const float* mlp1_g   = (const float*)d_in[25];
    const float* mlp1_bb  = (const float*)d_in[26];
    const float* mlp2_w   = (const float*)d_in[27];
    const float* mlp2_b   = (const float*)d_in[28];
    float* out = (float*)d_out;

    const int n = in_sizes[0] / FIN;          // 8192
    const int e = in_sizes[5];                // 262144
    const int k = e / n;                      // 32
    const int G = out_size;                   // 1024

    // 0) relabel residue ids + segment boundaries
    scan_pb_kernel<<<1, 1024>>>(pool_b, n);
    seg_bounds_kernel<<<(n + 255) / 256, 256>>>(n);

    // 1) node projections
    node_gemm_kernel<<<dim3(n / 32, 3), 128>>>(x, lin_w, lin_b, src_w, dst_w, n);

    // 2) fused edge attention (persistent blocks)
    attn_kernel<<<456, 128>>>(pos, normal, src,
                              posnn_w, posnn_b, posnn_g, posnn_bb,
                              attnn_w, attnn_b, attnn_g, attnn_bb, n, k);

    // 3) neck
    neck_kernel<<<dim3(n / 16, NECKD / 128), 128>>>(neck_w, neck_b, neck_g, neck_bb, n);

    // 4) residue max pool (+ mask pool)
    segmax_kernel<<<dim3(G, NECKD / 128), 128>>>(mask_t, G);

    // 5) head
    head_kernel<<<(G + 7) / 8, 256>>>(mlp1_w, mlp1_b, mlp1_g, mlp1_bb,
                                      mlp2_w, mlp2_b, out, G);
}

// round 5
// speedup vs baseline: 1.9272x; 1.9272x over previous
#include <cuda_runtime.h>
#include <cuda_bf16.h>
#include <cstdint>
#include <float.h>

#define HD    128
#define NECKD 512
#define FIN   59
#define NMAX  8192
#define KNB   32

// ---------------- scratch ----------------
__device__ float g_v   [NMAX * HD];
__device__ float g_asrc[NMAX * HD];
__device__ float g_adst[NMAX * HD];
__device__ float g_hout[NMAX * HD];
__device__ float g_hneck[NMAX * NECKD];
__device__ float g_gfeat[NMAX * NECKD];
__device__ int   g_pb[NMAX];
__device__ int   g_seg_start[NMAX];
__device__ int   g_seg_end[NMAX];
__device__ float g_mask_g[NMAX];

// ---------------- helpers ----------------
__device__ __forceinline__ float to_tf32(float x) {
    float r;
    asm("cvt.rna.tf32.f32 %0, %1;" : "=f"(r) : "f"(x));
    return r;
}
__device__ __forceinline__ void mma_tf32(float* acc, uint32_t a0, uint32_t a1,
                                         uint32_t a2, uint32_t a3,
                                         uint32_t b0, uint32_t b1) {
    asm volatile(
        "mma.sync.aligned.m16n8k8.row.col.f32.tf32.tf32.f32 "
        "{%0,%1,%2,%3}, {%4,%5,%6,%7}, {%8,%9}, {%0,%1,%2,%3};"
        : "+f"(acc[0]), "+f"(acc[1]), "+f"(acc[2]), "+f"(acc[3])
        : "r"(a0), "r"(a1), "r"(a2), "r"(a3), "r"(b0), "r"(b1));
}

// ---------------- K0a: relabel pool_batch -> pb ----------------
__global__ void scan_pb_kernel(const int* __restrict__ pool_batch, int n) {
    __shared__ int sums[1024];
    int t = threadIdx.x;
    int base = t * 8;
    int loc[8];
    int run = 0;
#pragma unroll
    for (int j = 0; j < 8; ++j) {
        int i = base + j;
        int chg = 0;
        if (i < n && i > 0) chg = (pool_batch[i] != pool_batch[i - 1]) ? 1 : 0;
        run += chg;
        loc[j] = run;
    }
    sums[t] = run;
    __syncthreads();
    for (int off = 1; off < 1024; off <<= 1) {
        int v = (t >= off) ? sums[t - off] : 0;
        __syncthreads();
        sums[t] += v;
        __syncthreads();
    }
    int offset = (t > 0) ? sums[t - 1] : 0;
#pragma unroll
    for (int j = 0; j < 8; ++j) {
        int i = base + j;
        if (i < n) g_pb[i] = offset + loc[j];
    }
}

__global__ void seg_bounds_kernel(int n) {
    int i = blockIdx.x * blockDim.x + threadIdx.x;
    if (i >= n) return;
    int g = g_pb[i];
    if (i == 0 || g_pb[i - 1] != g) g_seg_start[g] = i;
    if (i == n - 1 || g_pb[i + 1] != g) g_seg_end[g] = i + 1;
}

// ---------------- K1: node GEMMs ----------------
__global__ void __launch_bounds__(128, 2)
node_gemm_kernel(const float* __restrict__ x,
                 const float* __restrict__ lin_w, const float* __restrict__ lin_b,
                 const float* __restrict__ src_w, const float* __restrict__ dst_w,
                 int n) {
    int which = blockIdx.y;
    const float* W = (which == 0) ? lin_w : (which == 1) ? src_w : dst_w;
    float* out = (which == 0) ? g_v : (which == 1) ? g_asrc : g_adst;
    int h = threadIdx.x;

    float Wc[FIN];
#pragma unroll
    for (int c = 0; c < FIN; ++c) Wc[c] = W[c * HD + h];
    float bias = (which == 0) ? lin_b[h] : 0.0f;

    int r0 = blockIdx.x * 32;
    __shared__ float xs[32][FIN + 1];
    for (int idx = h; idx < 32 * FIN; idx += 128) {
        int r = idx / FIN, c = idx % FIN;
        xs[r][c] = x[(r0 + r) * FIN + c];
    }
    __syncthreads();
    for (int r = 0; r < 32; ++r) {
        float a = bias;
#pragma unroll
        for (int c = 0; c < FIN; ++c) a = fmaf(xs[r][c], Wc[c], a);
        out[(r0 + r) * HD + h] = a;
    }
}

// ---------------- K2: fused edge attention, tensor-core version ----------------
// Persistent blocks of 256 threads (8 warps). Tile = 2 nodes = 64 edges.
// alpha tile [64,128] = T [64,128] @ attnn_w [128,128] via mma.m16n8k8 tf32,
// 3-MMA split (AhBh + AlBh + AhBl) for fp32-grade accuracy.
// Smem float offsets:
//   WF  [0,      32768)  : W fragments {bh0,bh1,bl0,bl1} per (k0,ntg,lane)
//   AFh [32768,  40960)  : A-frag hi {a0..a3} per (k0,mt,lane)
//   AFl [40960,  49152)  : A-frag lo
//   U   [49152,  57408)  : u = v[src]+delta, [64][129]
//   REL [57408,  57920)  : [64][8] edge rel vectors
//   SS  [57920,  57984)  : src node per edge (int)
#define SM_WF   0
#define SM_AFH  32768
#define SM_AFL  40960
#define SM_U    49152
#define SM_REL  57408
#define SM_SS   57920
#define SM_FLOATS 57984
#define ATTN_SMEM_BYTES (SM_FLOATS * 4)

__global__ void __launch_bounds__(256, 1)
attn_mma_kernel(const float* __restrict__ pos, const float* __restrict__ normal,
                const int* __restrict__ src,
                const float* __restrict__ posnn_w, const float* __restrict__ posnn_b,
                const float* __restrict__ posnn_g, const float* __restrict__ posnn_bb,
                const float* __restrict__ attnn_w, const float* __restrict__ attnn_b,
                const float* __restrict__ attnn_g, const float* __restrict__ attnn_bb,
                int n) {
    extern __shared__ float sm[];
    float* WF  = sm + SM_WF;
    float* AFh = sm + SM_AFH;
    float* AFl = sm + SM_AFL;
    float* U   = sm + SM_U;
    float* REL = sm + SM_REL;
    int*   SS  = (int*)(sm + SM_SS);

    const int tid = threadIdx.x;
    const int w   = tid >> 5;      // warp 0..7
    const int l   = tid & 31;      // lane
    const float inv = rsqrtf(1.0f + 1e-5f);

    // ---- stage W fragments (hi/lo) once per block ----
    for (int slot = tid; slot < 16 * 16 * 32; slot += 256) {
        int k0  = slot >> 9;
        int ntg = (slot >> 5) & 15;
        int ll  = slot & 31;
        int krow = k0 * 8 + (ll & 3);
        int col  = ntg * 8 + (ll >> 2);
        float w0 = attnn_w[krow * HD + col];
        float w1 = attnn_w[(krow + 4) * HD + col];
        float bh0 = to_tf32(w0), bl0 = to_tf32(w0 - bh0);
        float bh1 = to_tf32(w1), bl1 = to_tf32(w1 - bh1);
        float4* p = (float4*)(WF + slot * 4);
        *p = make_float4(bh0, bh1, bl0, bl1);
    }

    // ---- per-lane phase-1 params: 4 channels cols[cc] = 16w + (l&3) + 4*cc ----
    float pw[6][4], ppb[4], ppg[4], ppbb[4];
#pragma unroll
    for (int cc = 0; cc < 4; ++cc) {
        int c = 16 * w + (l & 3) + 4 * cc;
#pragma unroll
        for (int j = 0; j < 6; ++j) pw[j][cc] = posnn_w[j * HD + c];
        ppb[cc]  = posnn_b[c];
        ppg[cc]  = posnn_g[c] * inv;
        ppbb[cc] = posnn_bb[c];
    }
    // ---- per-lane epilogue params: 8 cols c = (w&3)*32 + nt*8 + 2*(l&3) + j ----
    float eab[8], eag[8], eabb[8];
#pragma unroll
    for (int p = 0; p < 8; ++p) {
        int c = (w & 3) * 32 + (p >> 1) * 8 + 2 * (l & 3) + (p & 1);
        eab[p]  = attnn_b[c];
        eag[p]  = attnn_g[c] * inv;
        eabb[p] = attnn_bb[c];
    }
    __syncthreads();

    const int ntiles = n >> 1;
    for (int tt = blockIdx.x; tt < ntiles; tt += gridDim.x) {
        const int i0 = tt * 2;

        // ---- stage rel + src for the 64 edges ----
        if (tid < 64) {
            int e = tid;
            int node = i0 + (e >> 5);
            int s = src[i0 * KNB + e];
            SS[e] = s;
            float* r = REL + e * 8;
            r[0] = pos[3 * node]     - pos[3 * s];
            r[1] = pos[3 * node + 1] - pos[3 * s + 1];
            r[2] = pos[3 * node + 2] - pos[3 * s + 2];
            r[3] = normal[3 * node]     - normal[3 * s];
            r[4] = normal[3 * node + 1] - normal[3 * s + 1];
            r[5] = normal[3 * node + 2] - normal[3 * s + 2];
        }
        __syncthreads();

        // ---- adst hoist: 2 nodes x 4 lane-cols ----
        float adv[2][4];
#pragma unroll
        for (int nd = 0; nd < 2; ++nd)
#pragma unroll
            for (int cc = 0; cc < 4; ++cc)
                adv[nd][cc] = g_adst[(i0 + nd) * HD + 16 * w + (l & 3) + 4 * cc];

        // ---- phase 1: build A fragments (hi/lo) + U ----
#pragma unroll
        for (int mt = 0; mt < 4; ++mt) {
            int e1 = mt * 16 + (l >> 2);
            int e2 = e1 + 8;
            int nd = mt >> 1;
            int s1 = SS[e1], s2 = SS[e2];
            float r1[6], r2[6];
#pragma unroll
            for (int j = 0; j < 6; ++j) { r1[j] = REL[e1 * 8 + j]; r2[j] = REL[e2 * 8 + j]; }
#pragma unroll
            for (int kk = 0; kk < 2; ++kk) {
                int k0 = 2 * w + kk;
                float hi[4], lo[4];
#pragma unroll
                for (int aa = 0; aa < 2; ++aa) {
                    int cc = 2 * kk + aa;
                    int c = 16 * w + (l & 3) + 4 * cc;
                    // delta for edge1 / edge2, channel c
                    float d1 = ppb[cc], d2 = ppb[cc];
#pragma unroll
                    for (int j = 0; j < 6; ++j) {
                        d1 = fmaf(r1[j], pw[j][cc], d1);
                        d2 = fmaf(r2[j], pw[j][cc], d2);
                    }
                    d1 = fmaxf(fmaf(d1, ppg[cc], ppbb[cc]), 0.0f);
                    d2 = fmaxf(fmaf(d2, ppg[cc], ppbb[cc]), 0.0f);
                    float t1 = adv[nd][cc] - g_asrc[s1 * HD + c] + d1;
                    float t2 = adv[nd][cc] - g_asrc[s2 * HD + c] + d2;
                    U[e1 * 129 + c] = g_v[s1 * HD + c] + d1;
                    U[e2 * 129 + c] = g_v[s2 * HD + c] + d2;
                    float h1 = to_tf32(t1), h2 = to_tf32(t2);
                    hi[aa * 2 + 0] = h1; lo[aa * 2 + 0] = to_tf32(t1 - h1);
                    hi[aa * 2 + 1] = h2; lo[aa * 2 + 1] = to_tf32(t2 - h2);
                }
                int slot = ((k0 * 4 + mt) * 32 + l) * 4;
                *(float4*)(AFh + slot) = make_float4(hi[0], hi[1], hi[2], hi[3]);
                *(float4*)(AFl + slot) = make_float4(lo[0], lo[1], lo[2], lo[3]);
            }
        }
        __syncthreads();

        // ---- GEMM: warp (w>>2 = node/m-group, w&3 = n-group) ----
        float acc[2][4][4];
#pragma unroll
        for (int a = 0; a < 2; ++a)
#pragma unroll
            for (int b = 0; b < 4; ++b)
#pragma unroll
                for (int c = 0; c < 4; ++c) acc[a][b][c] = 0.0f;

        const int mbase = (w >> 2) * 2;
        const int nbase = (w & 3) * 4;
#pragma unroll 4
        for (int k0 = 0; k0 < 16; ++k0) {
            float4 AH[2], AL[2];
#pragma unroll
            for (int mtw = 0; mtw < 2; ++mtw) {
                int slot = ((k0 * 4 + (mbase + mtw)) * 32 + l) * 4;
                AH[mtw] = *(const float4*)(AFh + slot);
                AL[mtw] = *(const float4*)(AFl + slot);
            }
#pragma unroll
            for (int ntw = 0; ntw < 4; ++ntw) {
                float4 B = *(const float4*)(WF + ((k0 * 16 + (nbase + ntw)) * 32 + l) * 4);
                uint32_t bh0 = __float_as_uint(B.x), bh1 = __float_as_uint(B.y);
                uint32_t bl0 = __float_as_uint(B.z), bl1 = __float_as_uint(B.w);
#pragma unroll
                for (int mtw = 0; mtw < 2; ++mtw) {
                    uint32_t ah0 = __float_as_uint(AH[mtw].x), ah1 = __float_as_uint(AH[mtw].y);
                    uint32_t ah2 = __float_as_uint(AH[mtw].z), ah3 = __float_as_uint(AH[mtw].w);
                    uint32_t al0 = __float_as_uint(AL[mtw].x), al1 = __float_as_uint(AL[mtw].y);
                    uint32_t al2 = __float_as_uint(AL[mtw].z), al3 = __float_as_uint(AL[mtw].w);
                    mma_tf32(acc[mtw][ntw], ah0, ah1, ah2, ah3, bh0, bh1);
                    mma_tf32(acc[mtw][ntw], al0, al1, al2, al3, bh0, bh1);
                    mma_tf32(acc[mtw][ntw], ah0, ah1, ah2, ah3, bl0, bl1);
                }
            }
        }

        // ---- epilogue: bn_relu + per-node softmax over 32 edges + h-out ----
        const int node = i0 + (w >> 2);
#pragma unroll
        for (int ntw = 0; ntw < 4; ++ntw) {
#pragma unroll
            for (int j = 0; j < 2; ++j) {
                int p = ntw * 2 + j;
                int c = (w & 3) * 32 + ntw * 8 + 2 * (l & 3) + j;
                float x[2][2];
#pragma unroll
                for (int mtw = 0; mtw < 2; ++mtw)
#pragma unroll
                    for (int rr = 0; rr < 2; ++rr) {
                        float raw = acc[mtw][ntw][rr * 2 + j];
                        x[mtw][rr] = fmaxf(fmaf(raw + eab[p], eag[p], eabb[p]), 0.0f);
                    }
                float m = fmaxf(fmaxf(x[0][0], x[0][1]), fmaxf(x[1][0], x[1][1]));
                m = fmaxf(m, __shfl_xor_sync(0xffffffffu, m, 4));
                m = fmaxf(m, __shfl_xor_sync(0xffffffffu, m, 8));
                m = fmaxf(m, __shfl_xor_sync(0xffffffffu, m, 16));
                float se = 0.0f, sn = 0.0f;
#pragma unroll
                for (int mtw = 0; mtw < 2; ++mtw)
#pragma unroll
                    for (int rr = 0; rr < 2; ++rr) {
                        float pe = __expf(x[mtw][rr] - m);
                        int row = (w >> 2) * 32 + mtw * 16 + (l >> 2) + 8 * rr;
                        se += pe;
                        sn = fmaf(pe, U[row * 129 + c], sn);
                    }
                se += __shfl_xor_sync(0xffffffffu, se, 4);
                se += __shfl_xor_sync(0xffffffffu, se, 8);
                se += __shfl_xor_sync(0xffffffffu, se, 16);
                sn += __shfl_xor_sync(0xffffffffu, sn, 4);
                sn += __shfl_xor_sync(0xffffffffu, sn, 8);
                sn += __shfl_xor_sync(0xffffffffu, sn, 16);
                if ((l >> 2) == 0)
                    g_hout[node * HD + c] = sn / (se + 1e-16f);
            }
        }
        __syncthreads();   // protect AF/U before next tile's phase 1
    }
}

// ---------------- K3: neck GEMM + bn_relu ----------------
__global__ void __launch_bounds__(128, 2)
neck_kernel(const float* __restrict__ W, const float* __restrict__ b,
            const float* __restrict__ g, const float* __restrict__ bb, int n) {
    int col = blockIdx.y * 128 + threadIdx.x;
    float Wc[HD];
#pragma unroll
    for (int c = 0; c < HD; ++c) Wc[c] = W[c * NECKD + col];
    const float inv = rsqrtf(1.0f + 1e-5f);
    float bias = b[col], gg = g[col] * inv, sh = bb[col];

    int r0 = blockIdx.x * 16;
    __shared__ __align__(16) float hs[16][HD];
    for (int idx = threadIdx.x; idx < 16 * HD; idx += 128)
        ((float*)hs)[idx] = g_hout[r0 * HD + idx];
    __syncthreads();

    for (int r = 0; r < 16; ++r) {
        const float4* h4 = (const float4*)(hs[r]);
        float a0 = 0.f, a1 = 0.f, a2 = 0.f, a3 = 0.f;
#pragma unroll
        for (int c4 = 0; c4 < HD / 4; ++c4) {
            float4 tv = h4[c4];
            a0 = fmaf(tv.x, Wc[4 * c4 + 0], a0);
            a1 = fmaf(tv.y, Wc[4 * c4 + 1], a1);
            a2 = fmaf(tv.z, Wc[4 * c4 + 2], a2);
            a3 = fmaf(tv.w, Wc[4 * c4 + 3], a3);
        }
        float a = (a0 + a1) + (a2 + a3) + bias;
        g_hneck[(r0 + r) * NECKD + col] = fmaxf(fmaf(a, gg, sh), 0.0f);
    }
}

// ---------------- segmax ----------------
__global__ void segmax_kernel(const float* __restrict__ mask_t, int G) {
    int gidx = blockIdx.x;
    if (gidx >= G) return;
    int c = blockIdx.y * 128 + threadIdx.x;
    int s0 = g_seg_start[gidx], s1 = g_seg_end[gidx];
    float mx = -FLT_MAX;
    for (int i = s0; i < s1; ++i) mx = fmaxf(mx, g_hneck[i * NECKD + c]);
    g_gfeat[gidx * NECKD + c] = mx;
    if (blockIdx.y == 0 && threadIdx.x == 0) {
        float mm = -FLT_MAX;
        for (int i = s0; i < s1; ++i) mm = fmaxf(mm, mask_t[i]);
        g_mask_g[gidx] = mm;
    }
}

// ---------------- head ----------------
__global__ void __launch_bounds__(256)
head_kernel(const float* __restrict__ W1, const float* __restrict__ b1,
            const float* __restrict__ g1, const float* __restrict__ bb1,
            const float* __restrict__ W2, const float* __restrict__ b2,
            float* __restrict__ out, int G) {
    int t = threadIdx.x;
    int g0 = blockIdx.x * 8;
    __shared__ float gs[8][NECKD];
    for (int idx = t; idx < 8 * NECKD; idx += 256) {
        int gi = idx >> 9, c = idx & (NECKD - 1);
        gs[gi][c] = (g0 + gi < G) ? g_gfeat[(g0 + gi) * NECKD + c] : 0.0f;
    }
    __syncthreads();

    float acc[8] = {0, 0, 0, 0, 0, 0, 0, 0};
    for (int c = 0; c < NECKD; ++c) {
        float w = W1[c * 256 + t];
#pragma unroll
        for (int gi = 0; gi < 8; ++gi) acc[gi] = fmaf(gs[gi][c], w, acc[gi]);
    }

    const float inv = rsqrtf(1.0f + 1e-5f);
    float bias = b1[t], gg = g1[t] * inv, sh = bb1[t], w2 = W2[t];

    __shared__ float red[256];
    for (int gi = 0; gi < 8; ++gi) {
        float m1 = fmaxf(fmaf(acc[gi] + bias, gg, sh), 0.0f);
        red[t] = m1 * w2;
        __syncthreads();
        for (int off = 128; off > 0; off >>= 1) {
            if (t < off) red[t] += red[t + off];
            __syncthreads();
        }
        if (t == 0) {
            int g = g0 + gi;
            if (g < G) out[g] = (g_mask_g[g] == 1.0f) ? (red[0] + b2[0]) : 0.0f;
        }
        __syncthreads();
    }
}

// ---------------- launch ----------------
extern "C" void kernel_launch(void* const* d_in, const int* in_sizes, int n_in,
                              void* d_out, int out_size) {
    const float* x        = (const float*)d_in[0];
    const float* pos      = (const float*)d_in[1];
    const float* normal   = (const float*)d_in[2];
    const float* mask_t   = (const float*)d_in[3];
    const int*   pool_b   = (const int*)  d_in[4];
    const int*   src      = (const int*)  d_in[5];
    const float* lin_w    = (const float*)d_in[7];
    const float* lin_b    = (const float*)d_in[8];
    const float* src_w    = (const float*)d_in[9];
    const float* dst_w    = (const float*)d_in[10];
    const float* posnn_w  = (const float*)d_in[11];
    const float* posnn_b  = (const float*)d_in[12];
    const float* posnn_g  = (const float*)d_in[13];
    const float* posnn_bb = (const float*)d_in[14];
    const float* attnn_w  = (const float*)d_in[15];
    const float* attnn_b  = (const float*)d_in[16];
    const float* attnn_g  = (const float*)d_in[17];
    const float* attnn_bb = (const float*)d_in[18];
    const float* neck_w   = (const float*)d_in[19];
    const float* neck_b   = (const float*)d_in[20];
    const float* neck_g   = (const float*)d_in[21];
    const float* neck_bb  = (const float*)d_in[22];
    const float* mlp1_w   = (const float*)d_in[23];
    const float* mlp1_b   = (const float*)d_in[24];
    const float* mlp1_g   = (const float*)d_in[25];
    const float* mlp1_bb  = (const float*)d_in[26];
    const float* mlp2_w   = (const float*)d_in[27];
    const float* mlp2_b   = (const float*)d_in[28];
    float* out = (float*)d_out;

    const int n = in_sizes[0] / FIN;          // 8192
    const int G = out_size;                   // 1024

    static int smem_set = 0;
    if (!smem_set) {
        cudaFuncSetAttribute(attn_mma_kernel,
                             cudaFuncAttributeMaxDynamicSharedMemorySize,
                             ATTN_SMEM_BYTES);
        smem_set = 1;
    }

    scan_pb_kernel<<<1, 1024>>>(pool_b, n);
    seg_bounds_kernel<<<(n + 255) / 256, 256>>>(n);

    node_gemm_kernel<<<dim3(n / 32, 3), 128>>>(x, lin_w, lin_b, src_w, dst_w, n);

    attn_mma_kernel<<<152, 256, ATTN_SMEM_BYTES>>>(
        pos, normal, src,
        posnn_w, posnn_b, posnn_g, posnn_bb,
        attnn_w, attnn_b, attnn_g, attnn_bb, n);

    neck_kernel<<<dim3(n / 16, NECKD / 128), 128>>>(neck_w, neck_b, neck_g, neck_bb, n);

    segmax_kernel<<<dim3(G, NECKD / 128), 128>>>(mask_t, G);

    head_kernel<<<(G + 7) / 8, 256>>>(mlp1_w, mlp1_b, mlp1_g, mlp1_bb,
                                      mlp2_w, mlp2_b, out, G);
}